// round 15
// baseline (speedup 1.0000x reference)
#include <cuda_runtime.h>
#include <cuda_fp16.h>
#include <cstdint>

#define BB    8192
#define FF    64
#define VV    1000
#define NTOKN 16
#define GG    4
#define DD    256
#define KK    128
#define SBK   4
#define MT    64           // rows per group = SBK*NTOKN
#define NGRP  (BB / SBK)   // 2048
#define NTHR  512

#define PADB  272          // bytes per fp16 tile row (136 halves): conflict-free ldmatrix

// smem byte offsets  (~94KB -> 2 CTAs per SM)
#define OFF_BH   0                         // W fp16 [256][136]   69632 B
#define OFF_A    69632                     // x fp16 [64][136]    17408 B
#define OFF_QS0  87040                     // 256 ints
#define OFF_QS1  88064
#define OFF_GX   89088                     // 64 ints
#define OFF_BIA  89344                     // 256 floats
#define OFF_GAM  90368
#define OFF_BET  91392
#define OFF_PSUM 92416                     // [64][8] floats  2048 B
#define OFF_PSQ  94464                     // [64][8] floats  2048 B
#define OFF_FLAG 96512
#define SMEM_BYTES 96544

__device__ __forceinline__ uint32_t smem_u32(const void* p) {
    uint32_t a;
    asm("{ .reg .u64 t; cvta.to.shared.u64 t, %1; cvt.u32.u64 %0, t; }" : "=r"(a) : "l"(p));
    return a;
}
__device__ __forceinline__ void ldm4(uint32_t* r, uint32_t addr) {
    asm volatile("ldmatrix.sync.aligned.m8n8.x4.shared.b16 {%0,%1,%2,%3}, [%4];"
                 : "=r"(r[0]), "=r"(r[1]), "=r"(r[2]), "=r"(r[3]) : "r"(addr));
}
__device__ __forceinline__ void mma16816(float* c, const uint32_t* a,
                                         uint32_t b0, uint32_t b1) {
    asm volatile("mma.sync.aligned.m16n8k16.row.col.f32.f16.f16.f32 "
                 "{%0,%1,%2,%3}, {%4,%5,%6,%7}, {%8,%9}, {%0,%1,%2,%3};"
                 : "+f"(c[0]), "+f"(c[1]), "+f"(c[2]), "+f"(c[3])
                 : "r"(a[0]), "r"(a[1]), "r"(a[2]), "r"(a[3]), "r"(b0), "r"(b1));
}
__device__ __forceinline__ void stg_cs2(float* p, float x, float y) {
    asm volatile("st.global.cs.v2.f32 [%0], {%1,%2};" :: "l"(p), "f"(x), "f"(y) : "memory");
}
__device__ __forceinline__ float silu(float v) { return v / (1.f + __expf(-v)); }

__global__ __launch_bounds__(NTHR, 2)
void fused_tokenizer_kernel(const void*  __restrict__ ids_raw,
                            const int*   __restrict__ mask,
                            const int*   __restrict__ gidx,
                            const float* __restrict__ tbl,
                            const float* __restrict__ missing,
                            const float* __restrict__ W,
                            const float* __restrict__ bias,
                            const float* __restrict__ gamma,
                            const float* __restrict__ beta,
                            float*       __restrict__ out,
                            int nblocks)
{
    extern __shared__ char smem[];
    const uint32_t sb = smem_u32(smem);
    int*    gxS  = (int*)   (smem + OFF_GX);
    float*  bS   = (float*) (smem + OFF_BIA);
    float*  gS   = (float*) (smem + OFF_GAM);
    float*  btS  = (float*) (smem + OFF_BET);
    float*  psum = (float*) (smem + OFF_PSUM);
    float*  psq  = (float*) (smem + OFF_PSQ);
    int* qbuf[2] = { (int*)(smem + OFF_QS0), (int*)(smem + OFF_QS1) };

    const int tid  = threadIdx.x;
    const int wid  = tid >> 5;
    const int lane = tid & 31;

    // ---- One-time: W -> fp16 padded tile ----
    for (int i = tid; i < DD * KK; i += NTHR) {
        int n = i >> 7, k = i & 127;
        uint32_t off = (uint32_t)n * PADB + ((uint32_t)k << 1);
        *(__half*)(smem + OFF_BH + off) = __float2half_rn(W[i]);
    }
    if (tid < NTOKN * GG) gxS[tid] = gidx[tid];
    if (tid < DD) { bS[tid] = bias[tid]; gS[tid] = gamma[tid]; btS[tid] = beta[tid]; }
    // is64 detection: int64 ids < 1000 -> odd 32-bit words all zero
    if (tid < 32) {
        const unsigned int* p = (const unsigned int*)ids_raw;
        int ok = (p[1 + 2*tid] == 0u) & (p[65 + 2*tid] == 0u) &
                 (p[129 + 2*tid] == 0u) & (p[193 + 2*tid] == 0u);
        ok = __all_sync(0xffffffffu, ok);
        if (tid == 0) *(int*)(smem + OFF_FLAG) = ok;
    }
    __syncthreads();
    const int is64 = *(int*)(smem + OFF_FLAG);

    // ---- gather constants: warp owns (tt, mb); lane = (token-parity, e-quad) ----
    const int tt  = wid & 1;              // table half
    const int mb  = wid >> 1;             // 0..7
    const int t01 = lane >> 4;
    const int eq  = lane & 15;
    const int ntok = mb + t01 * 8;        // fixed token for this lane
    int fL[GG];
    #pragma unroll
    for (int g = 0; g < GG; ++g) fL[g] = gxS[ntok * GG + g];
    const float* gbase = tbl + (size_t)tt * 4096000 + (eq << 2);
    const float* mbase = missing + tt * 4096 + (eq << 2);
    char* aptr = smem + OFF_A + tt * 128 + eq * 8;      // + m*PADB per row

    // ---- GEMM warp mapping: 32m x 32n tiles (2m x 8n warp grid) ----
    const int mq = wid >> 3;              // 0..1  (32 rows)
    const int nq = wid & 7;               // 0..7  (32 cols)
    const uint32_t pa = sb + OFF_A + (uint32_t)(mq * 32 + (lane & 15)) * PADB
                      + (uint32_t)(lane >> 4) * 16;
    const uint32_t pb = sb + OFF_BH
                      + (uint32_t)(nq * 32 + (lane & 7) + ((lane >> 4) << 3)) * PADB
                      + (uint32_t)((lane >> 3) & 1) * 16;
    const int cbase = nq * 32 + (lane & 3) * 2;

    auto stage_q = [&](int g, int* buf) {
        if (tid < SBK * FF) {
            int gi  = g * (SBK * FF) + tid;
            int idv = is64 ? (int)__ldg((const long long*)ids_raw + gi)
                           : __ldg((const int*)ids_raw + gi);
            int f   = tid & 63;
            buf[tid] = (((f * VV + idv) << 6) << 1) | __ldg(mask + gi);
        }
    };
    auto gather = [&](const int* buf) {
        #pragma unroll
        for (int s = 0; s < SBK; ++s) {
            const int* q = buf + (s << 6);
            int qm[GG];
            #pragma unroll
            for (int g = 0; g < GG; ++g) qm[g] = q[fL[g]];
            float4 v[GG], w[GG];
            #pragma unroll
            for (int g = 0; g < GG; ++g)
                v[g] = __ldg((const float4*)(gbase + (qm[g] >> 1)));
            #pragma unroll
            for (int g = 0; g < GG; ++g)
                w[g] = __ldg((const float4*)(mbase + (fL[g] << 6)));  // L1-resident
            float x0 = 0.f, x1 = 0.f, x2 = 0.f, x3 = 0.f;
            #pragma unroll
            for (int g = 0; g < GG; ++g) {
                float mk = (float)(qm[g] & 1);
                x0 += v[g].x + mk * w[g].x;
                x1 += v[g].y + mk * w[g].y;
                x2 += v[g].z + mk * w[g].z;
                x3 += v[g].w + mk * w[g].w;
            }
            __half2 hp0 = __floats2half2_rn(x0 * 0.25f, x1 * 0.25f);
            __half2 hp1 = __floats2half2_rn(x2 * 0.25f, x3 * 0.25f);
            int m = (s << 4) + ntok;
            *(uint2*)(aptr + (uint32_t)m * PADB) =
                make_uint2(*(uint32_t*)&hp0, *(uint32_t*)&hp1);
        }
    };

    // ---- prologue ----
    int grp = blockIdx.x;
    stage_q(grp, qbuf[0]);
    __syncthreads();
    int qsel = 0;

    while (grp < NGRP) {
        // ---- gather(grp) -> A; stage q(next) under its latency ----
        gather(qbuf[qsel]);
        int nxt = grp + nblocks;
        if (nxt < NGRP) stage_q(nxt, qbuf[qsel ^ 1]);
        __syncthreads();   // A ready; q(nxt) staged; prev LN psum-reads done

        // ---- GEMM: 64x256x128 fp16 HMMA, warp tile 32x32 ----
        float acc[2][4][4];
        #pragma unroll
        for (int mf = 0; mf < 2; ++mf)
            #pragma unroll
            for (int nf = 0; nf < 4; ++nf)
                #pragma unroll
                for (int c = 0; c < 4; ++c) acc[mf][nf][c] = 0.f;

        #pragma unroll 1
        for (int s = 0; s < 8; ++s) {
            uint32_t a0[4], a1[4];
            ldm4(a0, pa + s * 32);
            ldm4(a1, pa + 16 * PADB + s * 32);
            uint32_t bc[4], bn[4];
            ldm4(bc, pb + s * 32);                // n-frags 0,1
            ldm4(bn, pb + 16 * PADB + s * 32);    // n-frags 2,3
            mma16816(acc[0][0], a0, bc[0], bc[1]);
            mma16816(acc[0][1], a0, bc[2], bc[3]);
            mma16816(acc[1][0], a1, bc[0], bc[1]);
            mma16816(acc[1][1], a1, bc[2], bc[3]);
            mma16816(acc[0][2], a0, bn[0], bn[1]);
            mma16816(acc[0][3], a0, bn[2], bn[3]);
            mma16816(acc[1][2], a1, bn[0], bn[1]);
            mma16816(acc[1][3], a1, bn[2], bn[3]);
        }

        // ---- bias + SiLU in regs; quad-reduce row partial sums ----
        float bsum[2][2] = {{0.f,0.f},{0.f,0.f}}, bsq[2][2] = {{0.f,0.f},{0.f,0.f}};
        #pragma unroll
        for (int nf = 0; nf < 4; ++nf) {
            int c = cbase + nf * 8;
            float2 bb = *(float2*)(bS + c);
            #pragma unroll
            for (int mf = 0; mf < 2; ++mf) {
                float v0 = silu(acc[mf][nf][0] + bb.x);
                float v1 = silu(acc[mf][nf][1] + bb.y);
                float v2 = silu(acc[mf][nf][2] + bb.x);
                float v3 = silu(acc[mf][nf][3] + bb.y);
                acc[mf][nf][0] = v0; acc[mf][nf][1] = v1;
                acc[mf][nf][2] = v2; acc[mf][nf][3] = v3;
                bsum[mf][0] += v0 + v1; bsq[mf][0] += v0*v0 + v1*v1;
                bsum[mf][1] += v2 + v3; bsq[mf][1] += v2*v2 + v3*v3;
            }
        }
        #pragma unroll
        for (int o = 1; o <= 2; o <<= 1) {
            #pragma unroll
            for (int mf = 0; mf < 2; ++mf)
                #pragma unroll
                for (int h = 0; h < 2; ++h) {
                    bsum[mf][h] += __shfl_xor_sync(0xffffffffu, bsum[mf][h], o);
                    bsq [mf][h] += __shfl_xor_sync(0xffffffffu, bsq [mf][h], o);
                }
        }
        if ((lane & 3) == 0) {
            #pragma unroll
            for (int mf = 0; mf < 2; ++mf) {
                int r = mq * 32 + mf * 16 + (lane >> 2);
                psum[r * 8 + nq] = bsum[mf][0];        psq[r * 8 + nq] = bsq[mf][0];
                psum[(r + 8) * 8 + nq] = bsum[mf][1];  psq[(r + 8) * 8 + nq] = bsq[mf][1];
            }
        }
        __syncthreads();   // psum ready; A reads complete (next gather may overwrite)

        // ---- LN params from partials + direct streaming stores ----
        #pragma unroll
        for (int mf = 0; mf < 2; ++mf)
            #pragma unroll
            for (int h = 0; h < 2; ++h) {
                int r = mq * 32 + mf * 16 + (lane >> 2) + h * 8;
                float4 p0 = *(float4*)(psum + r * 8);
                float4 p1 = *(float4*)(psum + r * 8 + 4);
                float4 q0 = *(float4*)(psq  + r * 8);
                float4 q1 = *(float4*)(psq  + r * 8 + 4);
                float mu  = (p0.x + p0.y + p0.z + p0.w +
                             p1.x + p1.y + p1.z + p1.w) * (1.f / 256.f);
                float var = (q0.x + q0.y + q0.z + q0.w +
                             q1.x + q1.y + q1.z + q1.w) * (1.f / 256.f) - mu * mu;
                float inv = rsqrtf(var + 1e-5f);
                float* dst = out + ((size_t)grp * MT + r) * DD;
                #pragma unroll
                for (int nf = 0; nf < 4; ++nf) {
                    int c = cbase + nf * 8;
                    float2 gg = *(float2*)(gS  + c);
                    float2 be = *(float2*)(btS + c);
                    stg_cs2(dst + c,
                            (acc[mf][nf][h*2+0] - mu) * inv * gg.x + be.x,
                            (acc[mf][nf][h*2+1] - mu) * inv * gg.y + be.y);
                }
            }

        grp = nxt; qsel ^= 1;
    }
}

extern "C" void kernel_launch(void* const* d_in, const int* in_sizes, int n_in,
                              void* d_out, int out_size) {
    const void*  ids     = d_in[0];
    const int*   mask    = (const int*)  d_in[1];
    const int*   gidx    = (const int*)  d_in[2];
    const float* tbl     = (const float*)d_in[3];
    const float* missing = (const float*)d_in[4];
    const float* W       = (const float*)d_in[5];
    const float* b       = (const float*)d_in[6];
    const float* gamma   = (const float*)d_in[7];
    const float* beta    = (const float*)d_in[8];
    float* out = (float*)d_out;

    int nsm = 0;
    cudaDeviceGetAttribute(&nsm, cudaDevAttrMultiProcessorCount, 0);
    if (nsm <= 0) nsm = 148;
    int nblk = 2 * nsm;                 // 2 CTAs per SM
    if (nblk > NGRP) nblk = NGRP;

    cudaFuncSetAttribute(fused_tokenizer_kernel,
                         cudaFuncAttributeMaxDynamicSharedMemorySize, SMEM_BYTES);

    fused_tokenizer_kernel<<<nblk, NTHR, SMEM_BYTES>>>(
        ids, mask, gidx, tbl, missing, W, b, gamma, beta, out, nblk);
}

// round 16
// speedup vs baseline: 1.1380x; 1.1380x over previous
#include <cuda_runtime.h>
#include <cuda_fp16.h>
#include <cstdint>

#define BB    8192
#define FF    64
#define VV    1000
#define NTOKN 16
#define GG    4
#define DD    256
#define KK    128
#define SBK   4
#define MT    64           // rows per group = SBK*NTOKN
#define NGRP  (BB / SBK)   // 2048
#define NTHR  512

#define PADB  272          // bytes per fp16 tile row (136 halves): conflict-free ldmatrix

// smem byte offsets  (~94KB -> 2 CTAs per SM)
#define OFF_BH   0                         // W*0.25 fp16 [256][136]  69632 B
#define OFF_A    69632                     // x fp16 [64][136]    17408 B
#define OFF_QS0  87040                     // 256 ints
#define OFF_QS1  88064
#define OFF_GX   89088                     // 64 ints
#define OFF_BIA  89344                     // 256 floats
#define OFF_GAM  90368
#define OFF_BET  91392
#define OFF_PSS  92416                     // [64][8] float2 {sum,sq}  4096 B
#define OFF_FLAG 96512
#define SMEM_BYTES 96544

__device__ __forceinline__ uint32_t smem_u32(const void* p) {
    uint32_t a;
    asm("{ .reg .u64 t; cvta.to.shared.u64 t, %1; cvt.u32.u64 %0, t; }" : "=r"(a) : "l"(p));
    return a;
}
__device__ __forceinline__ void ldm4(uint32_t* r, uint32_t addr) {
    asm volatile("ldmatrix.sync.aligned.m8n8.x4.shared.b16 {%0,%1,%2,%3}, [%4];"
                 : "=r"(r[0]), "=r"(r[1]), "=r"(r[2]), "=r"(r[3]) : "r"(addr));
}
__device__ __forceinline__ void mma16816(float* c, const uint32_t* a,
                                         uint32_t b0, uint32_t b1) {
    asm volatile("mma.sync.aligned.m16n8k16.row.col.f32.f16.f16.f32 "
                 "{%0,%1,%2,%3}, {%4,%5,%6,%7}, {%8,%9}, {%0,%1,%2,%3};"
                 : "+f"(c[0]), "+f"(c[1]), "+f"(c[2]), "+f"(c[3])
                 : "r"(a[0]), "r"(a[1]), "r"(a[2]), "r"(a[3]), "r"(b0), "r"(b1));
}
__device__ __forceinline__ void stg_cs2(float* p, float x, float y) {
    asm volatile("st.global.cs.v2.f32 [%0], {%1,%2};" :: "l"(p), "f"(x), "f"(y) : "memory");
}
// silu via MUFU.TANH (1 MUFU instead of EX2+RCP): v * (0.5*tanh(v/2)+0.5)
__device__ __forceinline__ float silu(float v) {
    float t;
    asm("tanh.approx.f32 %0, %1;" : "=f"(t) : "f"(v * 0.5f));
    return v * fmaf(0.5f, t, 0.5f);
}

__global__ __launch_bounds__(NTHR, 2)
void fused_tokenizer_kernel(const void*  __restrict__ ids_raw,
                            const int*   __restrict__ mask,
                            const int*   __restrict__ gidx,
                            const float* __restrict__ tbl,
                            const float* __restrict__ missing,
                            const float* __restrict__ W,
                            const float* __restrict__ bias,
                            const float* __restrict__ gamma,
                            const float* __restrict__ beta,
                            float*       __restrict__ out,
                            int nblocks)
{
    extern __shared__ char smem[];
    const uint32_t sb = smem_u32(smem);
    int*    gxS  = (int*)   (smem + OFF_GX);
    float*  bS   = (float*) (smem + OFF_BIA);
    float*  gS   = (float*) (smem + OFF_GAM);
    float*  btS  = (float*) (smem + OFF_BET);
    float2* pss  = (float2*)(smem + OFF_PSS);
    int* qbuf[2] = { (int*)(smem + OFF_QS0), (int*)(smem + OFF_QS1) };

    const int tid  = threadIdx.x;
    const int wid  = tid >> 5;
    const int lane = tid & 31;

    // ---- One-time: W*0.25 -> fp16 padded tile (folds the group-mean 1/4) ----
    for (int i = tid; i < DD * KK; i += NTHR) {
        int n = i >> 7, k = i & 127;
        uint32_t off = (uint32_t)n * PADB + ((uint32_t)k << 1);
        *(__half*)(smem + OFF_BH + off) = __float2half_rn(W[i] * 0.25f);
    }
    if (tid < NTOKN * GG) gxS[tid] = gidx[tid];
    if (tid < DD) { bS[tid] = bias[tid]; gS[tid] = gamma[tid]; btS[tid] = beta[tid]; }
    // is64 detection: int64 ids < 1000 -> odd 32-bit words all zero
    if (tid < 32) {
        const unsigned int* p = (const unsigned int*)ids_raw;
        int ok = (p[1 + 2*tid] == 0u) & (p[65 + 2*tid] == 0u) &
                 (p[129 + 2*tid] == 0u) & (p[193 + 2*tid] == 0u);
        ok = __all_sync(0xffffffffu, ok);
        if (tid == 0) *(int*)(smem + OFF_FLAG) = ok;
    }
    __syncthreads();
    const int is64 = *(int*)(smem + OFF_FLAG);

    // ---- gather constants: warp owns (tt, mb); lane = (token-parity, e-quad) ----
    const int tt  = wid & 1;              // table half
    const int mb  = wid >> 1;             // 0..7
    const int t01 = lane >> 4;
    const int eq  = lane & 15;
    const int ntok = mb + t01 * 8;        // fixed token for this lane
    int fL[GG];
    #pragma unroll
    for (int g = 0; g < GG; ++g) fL[g] = gxS[ntok * GG + g];
    const float* gbase = tbl + (size_t)tt * 4096000 + (eq << 2);
    const float* mbase = missing + tt * 4096 + (eq << 2);
    char* aptr = smem + OFF_A + tt * 128 + eq * 8;      // + m*PADB per row

    // ---- GEMM warp mapping: 32m x 32n tiles (2m x 8n warp grid) ----
    const int mq = wid >> 3;              // 0..1  (32 rows)
    const int nq = wid & 7;               // 0..7  (32 cols)
    const uint32_t pa = sb + OFF_A + (uint32_t)(mq * 32 + (lane & 15)) * PADB
                      + (uint32_t)(lane >> 4) * 16;
    const uint32_t pb = sb + OFF_BH
                      + (uint32_t)(nq * 32 + (lane & 7) + ((lane >> 4) << 3)) * PADB
                      + (uint32_t)((lane >> 3) & 1) * 16;
    const int cbase = nq * 32 + (lane & 3) * 2;

    auto stage_q = [&](int g, int* buf) {
        if (tid < SBK * FF) {
            int gi  = g * (SBK * FF) + tid;
            int idv = is64 ? (int)__ldg((const long long*)ids_raw + gi)
                           : __ldg((const int*)ids_raw + gi);
            int f   = tid & 63;
            buf[tid] = (((f * VV + idv) << 6) << 1) | __ldg(mask + gi);
        }
    };
    auto gather = [&](const int* buf) {
        #pragma unroll
        for (int s = 0; s < SBK; ++s) {
            const int* q = buf + (s << 6);
            int qm[GG];
            #pragma unroll
            for (int g = 0; g < GG; ++g) qm[g] = q[fL[g]];
            float4 v[GG], w[GG];
            #pragma unroll
            for (int g = 0; g < GG; ++g)
                v[g] = __ldg((const float4*)(gbase + (qm[g] >> 1)));
            #pragma unroll
            for (int g = 0; g < GG; ++g)
                w[g] = __ldg((const float4*)(mbase + (fL[g] << 6)));  // L1-resident
            float x0 = 0.f, x1 = 0.f, x2 = 0.f, x3 = 0.f;
            #pragma unroll
            for (int g = 0; g < GG; ++g) {
                float mk = (float)(qm[g] & 1);
                x0 += v[g].x + mk * w[g].x;
                x1 += v[g].y + mk * w[g].y;
                x2 += v[g].z + mk * w[g].z;
                x3 += v[g].w + mk * w[g].w;
            }
            // 0.25 mean factor folded into W staging
            __half2 hp0 = __floats2half2_rn(x0, x1);
            __half2 hp1 = __floats2half2_rn(x2, x3);
            int m = (s << 4) + ntok;
            *(uint2*)(aptr + (uint32_t)m * PADB) =
                make_uint2(*(uint32_t*)&hp0, *(uint32_t*)&hp1);
        }
    };

    // ---- prologue ----
    int grp = blockIdx.x;
    stage_q(grp, qbuf[0]);
    __syncthreads();
    int qsel = 0;

    while (grp < NGRP) {
        // ---- gather(grp) -> A; stage q(next) under its latency ----
        gather(qbuf[qsel]);
        int nxt = grp + nblocks;
        if (nxt < NGRP) stage_q(nxt, qbuf[qsel ^ 1]);
        __syncthreads();   // A ready; q(nxt) staged; prev LN psum-reads done

        // ---- GEMM: 64x256x128 fp16 HMMA, warp tile 32x32 ----
        float acc[2][4][4];
        #pragma unroll
        for (int mf = 0; mf < 2; ++mf)
            #pragma unroll
            for (int nf = 0; nf < 4; ++nf)
                #pragma unroll
                for (int c = 0; c < 4; ++c) acc[mf][nf][c] = 0.f;

        #pragma unroll 1
        for (int s = 0; s < 8; ++s) {
            uint32_t a0[4], a1[4];
            ldm4(a0, pa + s * 32);
            ldm4(a1, pa + 16 * PADB + s * 32);
            uint32_t bc[4], bn[4];
            ldm4(bc, pb + s * 32);                // n-frags 0,1
            ldm4(bn, pb + 16 * PADB + s * 32);    // n-frags 2,3
            mma16816(acc[0][0], a0, bc[0], bc[1]);
            mma16816(acc[0][1], a0, bc[2], bc[3]);
            mma16816(acc[1][0], a1, bc[0], bc[1]);
            mma16816(acc[1][1], a1, bc[2], bc[3]);
            mma16816(acc[0][2], a0, bn[0], bn[1]);
            mma16816(acc[0][3], a0, bn[2], bn[3]);
            mma16816(acc[1][2], a1, bn[0], bn[1]);
            mma16816(acc[1][3], a1, bn[2], bn[3]);
        }

        // ---- bias + SiLU in regs; quad-reduce row partial sums ----
        float bsum[2][2] = {{0.f,0.f},{0.f,0.f}}, bsq[2][2] = {{0.f,0.f},{0.f,0.f}};
        #pragma unroll
        for (int nf = 0; nf < 4; ++nf) {
            int c = cbase + nf * 8;
            float2 bb = *(float2*)(bS + c);
            #pragma unroll
            for (int mf = 0; mf < 2; ++mf) {
                float v0 = silu(acc[mf][nf][0] + bb.x);
                float v1 = silu(acc[mf][nf][1] + bb.y);
                float v2 = silu(acc[mf][nf][2] + bb.x);
                float v3 = silu(acc[mf][nf][3] + bb.y);
                acc[mf][nf][0] = v0; acc[mf][nf][1] = v1;
                acc[mf][nf][2] = v2; acc[mf][nf][3] = v3;
                bsum[mf][0] += v0 + v1; bsq[mf][0] += v0*v0 + v1*v1;
                bsum[mf][1] += v2 + v3; bsq[mf][1] += v2*v2 + v3*v3;
            }
        }
        #pragma unroll
        for (int o = 1; o <= 2; o <<= 1) {
            #pragma unroll
            for (int mf = 0; mf < 2; ++mf)
                #pragma unroll
                for (int h = 0; h < 2; ++h) {
                    bsum[mf][h] += __shfl_xor_sync(0xffffffffu, bsum[mf][h], o);
                    bsq [mf][h] += __shfl_xor_sync(0xffffffffu, bsq [mf][h], o);
                }
        }
        if ((lane & 3) == 0) {
            #pragma unroll
            for (int mf = 0; mf < 2; ++mf) {
                int r = mq * 32 + mf * 16 + (lane >> 2);
                pss[r * 8 + nq]       = make_float2(bsum[mf][0], bsq[mf][0]);
                pss[(r + 8) * 8 + nq] = make_float2(bsum[mf][1], bsq[mf][1]);
            }
        }
        __syncthreads();   // pss ready; A reads complete (next gather may overwrite)

        // ---- LN params from partials + direct streaming stores ----
        #pragma unroll
        for (int mf = 0; mf < 2; ++mf)
            #pragma unroll
            for (int h = 0; h < 2; ++h) {
                int r = mq * 32 + mf * 16 + (lane >> 2) + h * 8;
                const float4* pr = (const float4*)(pss + r * 8);
                float4 u0 = pr[0], u1 = pr[1], u2 = pr[2], u3 = pr[3];
                float sm = u0.x + u0.z + u1.x + u1.z + u2.x + u2.z + u3.x + u3.z;
                float qq = u0.y + u0.w + u1.y + u1.w + u2.y + u2.w + u3.y + u3.w;
                float mu  = sm * (1.f / 256.f);
                float var = qq * (1.f / 256.f) - mu * mu;
                float inv = rsqrtf(var + 1e-5f);
                float* dst = out + ((size_t)grp * MT + r) * DD;
                #pragma unroll
                for (int nf = 0; nf < 4; ++nf) {
                    int c = cbase + nf * 8;
                    float2 gg = *(float2*)(gS  + c);
                    float2 be = *(float2*)(btS + c);
                    stg_cs2(dst + c,
                            (acc[mf][nf][h*2+0] - mu) * inv * gg.x + be.x,
                            (acc[mf][nf][h*2+1] - mu) * inv * gg.y + be.y);
                }
            }

        grp = nxt; qsel ^= 1;
    }
}

extern "C" void kernel_launch(void* const* d_in, const int* in_sizes, int n_in,
                              void* d_out, int out_size) {
    const void*  ids     = d_in[0];
    const int*   mask    = (const int*)  d_in[1];
    const int*   gidx    = (const int*)  d_in[2];
    const float* tbl     = (const float*)d_in[3];
    const float* missing = (const float*)d_in[4];
    const float* W       = (const float*)d_in[5];
    const float* b       = (const float*)d_in[6];
    const float* gamma   = (const float*)d_in[7];
    const float* beta    = (const float*)d_in[8];
    float* out = (float*)d_out;

    int nsm = 0;
    cudaDeviceGetAttribute(&nsm, cudaDevAttrMultiProcessorCount, 0);
    if (nsm <= 0) nsm = 148;
    int nblk = 2 * nsm;                 // 2 CTAs per SM
    if (nblk > NGRP) nblk = NGRP;

    cudaFuncSetAttribute(fused_tokenizer_kernel,
                         cudaFuncAttributeMaxDynamicSharedMemorySize, SMEM_BYTES);

    fused_tokenizer_kernel<<<nblk, NTHR, SMEM_BYTES>>>(
        ids, mask, gidx, tbl, missing, W, b, gamma, beta, out, nblk);
}